// round 2
// baseline (speedup 1.0000x reference)
#include <cuda_runtime.h>
#include <math.h>

// ---------------------------------------------------------------------------
// LSTM layer: B=32, T=512, D=1024, H=1024
//   xp[t][b][g*1024+j] = sum_d x[b][t][d] * W_g[d][j] + b_g[j]
//   recurrence over t: z = xp[t] + h @ U  (4 gates), c/h update
//   out[b][t][:] = relu(states[t][b][:] @ W_o + b_o)
// ---------------------------------------------------------------------------

#define BB 32
#define TT 512
#define DD 1024
#define HH 1024

// Scratch (device globals: allocation-free rule)
__device__ float g_xp[(size_t)TT * BB * 4 * HH];      // 256 MB  [t][b][gate][j]
__device__ float g_states[(size_t)TT * BB * HH];      // 64 MB   [t][b][j]
__device__ unsigned g_bar_count = 0;
__device__ unsigned g_bar_gen = 0;

// ---------------------------------------------------------------------------
// Kernel 1: input projection GEMM.  M=16384 (m = t*32+b), N=4096, K=1024
// Tile 64x64, BK=16, 256 threads, 4x4 per thread.
// ---------------------------------------------------------------------------
__global__ void __launch_bounds__(256) k_input_gemm(
    const float* __restrict__ x,
    const float* __restrict__ Wi, const float* __restrict__ Wf,
    const float* __restrict__ Wg, const float* __restrict__ Wc,
    const float* __restrict__ bi, const float* __restrict__ bf,
    const float* __restrict__ bg, const float* __restrict__ bc)
{
    __shared__ float As[16][68];   // transposed A tile [k][m], padded
    __shared__ float Bs[16][64];   // B tile [k][n]

    const int tid = threadIdx.x;
    const int tx = tid & 15;       // n sub-tile
    const int ty = tid >> 4;       // m sub-tile
    const int nblk = blockIdx.x * 64;   // column in [0,4096)
    const int mblk = blockIdx.y * 64;

    const int gate = nblk >> 10;
    const float* W    = (gate == 0) ? Wi : (gate == 1) ? Wf : (gate == 2) ? Wg : Wc;
    const float* bias = (gate == 0) ? bi : (gate == 1) ? bf : (gate == 2) ? bg : bc;
    const int jb = nblk & 1023;

    // A-tile loader: thread loads one float4 from one row
    const int ar = tid >> 2;            // 0..63 (row in tile)
    const int ac = (tid & 3) << 2;      // 0..12 (k offset)
    const int am = mblk + ar;           // m = t*32 + b
    const float* arow = x + ((size_t)(am & 31) * TT + (am >> 5)) * DD;

    // B-tile loader
    const int br  = tid >> 4;           // 0..15 (k in tile)
    const int bc4 = (tid & 15) << 2;    // 0..60 (n offset)

    float acc[4][4] = {};

    for (int k0 = 0; k0 < DD; k0 += 16) {
        float4 av = *(const float4*)&arow[k0 + ac];
        float4 bv = *(const float4*)&W[(size_t)(k0 + br) * HH + jb + bc4];
        __syncthreads();
        As[ac + 0][ar] = av.x;
        As[ac + 1][ar] = av.y;
        As[ac + 2][ar] = av.z;
        As[ac + 3][ar] = av.w;
        *(float4*)&Bs[br][bc4] = bv;
        __syncthreads();
#pragma unroll
        for (int kk = 0; kk < 16; ++kk) {
            float4 a4 = *(const float4*)&As[kk][ty * 4];
            float4 b4 = *(const float4*)&Bs[kk][tx * 4];
            float avr[4] = {a4.x, a4.y, a4.z, a4.w};
            float bvr[4] = {b4.x, b4.y, b4.z, b4.w};
#pragma unroll
            for (int r = 0; r < 4; ++r)
#pragma unroll
                for (int c = 0; c < 4; ++c)
                    acc[r][c] = fmaf(avr[r], bvr[c], acc[r][c]);
        }
    }

    float4 bsv = *(const float4*)&bias[jb + tx * 4];
#pragma unroll
    for (int r = 0; r < 4; ++r) {
        const int m = mblk + ty * 4 + r;
        float4 o;
        o.x = acc[r][0] + bsv.x;
        o.y = acc[r][1] + bsv.y;
        o.z = acc[r][2] + bsv.z;
        o.w = acc[r][3] + bsv.w;
        *(float4*)&g_xp[(size_t)m * 4096 + nblk + tx * 4] = o;
    }
}

// ---------------------------------------------------------------------------
// Kernel 2: persistent recurrent kernel.
// Grid: 128 blocks x 256 threads (1 block/SM guaranteed -> custom grid sync ok)
// Block owns 8 j-columns (jbase = blockIdx*8). Thread owns (b = tid>>3, j).
// Per step: z_g[b][j] = xp[t][b][g][j] + sum_k h[b][k] * U_g[k][j]
// c kept in a register per thread across all 512 steps.
// ---------------------------------------------------------------------------
#define NBLK2 128
#define KT 64
#define HSTRIDE 1028                    // padded row stride for sh_h
#define USTRIDE 68                      // padded k stride for sh_u
#define SMEM2_FLOATS (32 * HSTRIDE + 4 * 8 * USTRIDE)

__device__ __forceinline__ void grid_sync()
{
    __syncthreads();
    if (threadIdx.x == 0) {
        __threadfence();
        unsigned gen = *(volatile unsigned*)&g_bar_gen;
        unsigned t = atomicAdd(&g_bar_count, 1);
        if (t == NBLK2 - 1) {
            g_bar_count = 0;
            __threadfence();
            atomicExch(&g_bar_gen, gen + 1);
        } else {
            while (*(volatile unsigned*)&g_bar_gen == gen) { }
            __threadfence();
        }
    }
    __syncthreads();
}

__global__ void __launch_bounds__(256, 1) k_recurrent(
    const float* __restrict__ Ui, const float* __restrict__ Uf,
    const float* __restrict__ Ug, const float* __restrict__ Uc)
{
    extern __shared__ float smem[];
    float* sh_h = smem;                        // [32][HSTRIDE]
    float* sh_u = smem + 32 * HSTRIDE;         // [4][8][USTRIDE]

    const int tid = threadIdx.x;
    const int jl = tid & 7;
    const int b  = tid >> 3;                   // 0..31
    const int jbase = blockIdx.x * 8;
    const int j = jbase + jl;

    float c = 0.0f;

    for (int t = 0; t < TT; ++t) {
        // ---- stage h_{t-1} into shared ----
        if (t == 0) {
            for (int i = tid; i < 32 * HSTRIDE; i += 256) smem[i] = 0.0f;
        } else {
            const float* hp = g_states + (size_t)(t - 1) * BB * HH;
            for (int i = tid; i < 8192; i += 256) {
                int bb = i >> 8;
                int k4 = (i & 255) << 2;
                float4 v = *(const float4*)&hp[bb * HH + k4];
                *(float4*)&sh_h[bb * HSTRIDE + k4] = v;
            }
        }
        __syncthreads();

        float a0 = 0.f, a1 = 0.f, a2 = 0.f, a3 = 0.f;

        for (int kt = 0; kt < HH; kt += KT) {
            // ---- stage U tiles for 4 gates, transposed to [g][j][k] ----
#pragma unroll
            for (int it = 0; it < 2; ++it) {
                int i = tid + it * 256;            // 0..511
                int g  = i >> 7;
                int r  = i & 127;
                int kk = r >> 1;
                int j4 = (r & 1) << 2;
                const float* Up = (g == 0) ? Ui : (g == 1) ? Uf : (g == 2) ? Ug : Uc;
                float4 v = *(const float4*)&Up[(size_t)(kt + kk) * HH + jbase + j4];
                float* d = &sh_u[(g * 8 + j4) * USTRIDE + kk];
                d[0 * USTRIDE] = v.x;
                d[1 * USTRIDE] = v.y;
                d[2 * USTRIDE] = v.z;
                d[3 * USTRIDE] = v.w;
            }
            __syncthreads();

            const float* hrow = &sh_h[b * HSTRIDE + kt];
            const float* u0p = &sh_u[(0 * 8 + jl) * USTRIDE];
            const float* u1p = &sh_u[(1 * 8 + jl) * USTRIDE];
            const float* u2p = &sh_u[(2 * 8 + jl) * USTRIDE];
            const float* u3p = &sh_u[(3 * 8 + jl) * USTRIDE];

#pragma unroll
            for (int kk = 0; kk < KT; kk += 4) {
                float4 hv = *(const float4*)&hrow[kk];
                float4 u0 = *(const float4*)&u0p[kk];
                float4 u1 = *(const float4*)&u1p[kk];
                float4 u2 = *(const float4*)&u2p[kk];
                float4 u3 = *(const float4*)&u3p[kk];
                a0 = fmaf(hv.x, u0.x, a0); a0 = fmaf(hv.y, u0.y, a0);
                a0 = fmaf(hv.z, u0.z, a0); a0 = fmaf(hv.w, u0.w, a0);
                a1 = fmaf(hv.x, u1.x, a1); a1 = fmaf(hv.y, u1.y, a1);
                a1 = fmaf(hv.z, u1.z, a1); a1 = fmaf(hv.w, u1.w, a1);
                a2 = fmaf(hv.x, u2.x, a2); a2 = fmaf(hv.y, u2.y, a2);
                a2 = fmaf(hv.z, u2.z, a2); a2 = fmaf(hv.w, u2.w, a2);
                a3 = fmaf(hv.x, u3.x, a3); a3 = fmaf(hv.y, u3.y, a3);
                a3 = fmaf(hv.z, u3.z, a3); a3 = fmaf(hv.w, u3.w, a3);
            }
            __syncthreads();
        }

        // ---- gates + state update ----
        const float* xp = g_xp + ((size_t)t * BB + b) * 4096;
        float zi = a0 + xp[0 * HH + j];
        float zf = a1 + xp[1 * HH + j];
        float zg = a2 + xp[2 * HH + j];
        float zc = a3 + xp[3 * HH + j];

        float ig = 1.0f / (1.0f + __expf(-zi));
        float fg = 1.0f / (1.0f + __expf(-zf));
        float gg = 1.0f / (1.0f + __expf(-zg));
        float ct = tanhf(zc);
        c = fg * c + ig * ct;
        float h = gg * tanhf(c);

        g_states[((size_t)t * BB + b) * HH + j] = h;

        grid_sync();
    }
}

// ---------------------------------------------------------------------------
// Kernel 3: output projection + ReLU.  M=16384 (rows of g_states, contiguous),
// N=1024, K=1024.  out[b][t][j], where row m = t*32 + b.
// ---------------------------------------------------------------------------
__global__ void __launch_bounds__(256) k_output_gemm(
    const float* __restrict__ Wo, const float* __restrict__ bo,
    float* __restrict__ out)
{
    __shared__ float As[16][68];
    __shared__ float Bs[16][64];

    const int tid = threadIdx.x;
    const int tx = tid & 15;
    const int ty = tid >> 4;
    const int nblk = blockIdx.x * 64;
    const int mblk = blockIdx.y * 64;

    const int ar = tid >> 2;
    const int ac = (tid & 3) << 2;
    const float* arow = g_states + (size_t)(mblk + ar) * HH;

    const int br  = tid >> 4;
    const int bc4 = (tid & 15) << 2;

    float acc[4][4] = {};

    for (int k0 = 0; k0 < HH; k0 += 16) {
        float4 av = *(const float4*)&arow[k0 + ac];
        float4 bv = *(const float4*)&Wo[(size_t)(k0 + br) * HH + nblk + bc4];
        __syncthreads();
        As[ac + 0][ar] = av.x;
        As[ac + 1][ar] = av.y;
        As[ac + 2][ar] = av.z;
        As[ac + 3][ar] = av.w;
        *(float4*)&Bs[br][bc4] = bv;
        __syncthreads();
#pragma unroll
        for (int kk = 0; kk < 16; ++kk) {
            float4 a4 = *(const float4*)&As[kk][ty * 4];
            float4 b4 = *(const float4*)&Bs[kk][tx * 4];
            float avr[4] = {a4.x, a4.y, a4.z, a4.w};
            float bvr[4] = {b4.x, b4.y, b4.z, b4.w};
#pragma unroll
            for (int r = 0; r < 4; ++r)
#pragma unroll
                for (int cix = 0; cix < 4; ++cix)
                    acc[r][cix] = fmaf(avr[r], bvr[cix], acc[r][cix]);
        }
    }

    float4 bsv = *(const float4*)&bo[nblk + tx * 4];
#pragma unroll
    for (int r = 0; r < 4; ++r) {
        const int m = mblk + ty * 4 + r;        // m = t*32 + b
        const int bidx = m & 31;
        const int tidx = m >> 5;
        float4 o;
        o.x = fmaxf(acc[r][0] + bsv.x, 0.0f);
        o.y = fmaxf(acc[r][1] + bsv.y, 0.0f);
        o.z = fmaxf(acc[r][2] + bsv.z, 0.0f);
        o.w = fmaxf(acc[r][3] + bsv.w, 0.0f);
        *(float4*)&out[((size_t)bidx * TT + tidx) * HH + nblk + tx * 4] = o;
    }
}

// ---------------------------------------------------------------------------
// Launch
// ---------------------------------------------------------------------------
extern "C" void kernel_launch(void* const* d_in, const int* in_sizes, int n_in,
                              void* d_out, int out_size)
{
    const float* x  = (const float*)d_in[0];
    const float* Wi = (const float*)d_in[1];
    const float* Ui = (const float*)d_in[2];
    const float* Wf = (const float*)d_in[3];
    const float* Uf = (const float*)d_in[4];
    const float* Wg = (const float*)d_in[5];
    const float* Ug = (const float*)d_in[6];
    const float* Wc = (const float*)d_in[7];
    const float* Uc = (const float*)d_in[8];
    const float* Wo = (const float*)d_in[9];
    const float* bi = (const float*)d_in[10];
    const float* bf = (const float*)d_in[11];
    const float* bg = (const float*)d_in[12];
    const float* bc = (const float*)d_in[13];
    const float* bo = (const float*)d_in[14];
    float* out = (float*)d_out;

    const int smem2 = SMEM2_FLOATS * (int)sizeof(float);   // ~140 KB
    cudaFuncSetAttribute(k_recurrent,
                         cudaFuncAttributeMaxDynamicSharedMemorySize, smem2);

    // 1) input projection: grid (4096/64, 16384/64)
    k_input_gemm<<<dim3(64, 256), 256>>>(x, Wi, Wf, Wg, Wc, bi, bf, bg, bc);

    // 2) recurrence: persistent kernel, 128 blocks (<=148 SMs, 1 blk/SM)
    k_recurrent<<<NBLK2, 256, smem2>>>(Ui, Uf, Ug, Uc);

    // 3) output projection: grid (1024/64, 16384/64)
    k_output_gemm<<<dim3(16, 256), 256>>>(Wo, bo, out);
}

// round 3
// speedup vs baseline: 2.0945x; 2.0945x over previous
#include <cuda_runtime.h>
#include <math.h>

// ---------------------------------------------------------------------------
// LSTM layer: B=32, T=512, D=1024, H=1024
//   k1: xp[t*32+b][g*1024+j] = sum_d x[b][t][d] * W_g[d][j] + b_g[j]
//   k2: recurrence over t (persistent kernel, grid sync per step)
//   k3: out[b][t][:] = relu(states[t*32+b][:] @ W_o + b_o)
// ---------------------------------------------------------------------------

#define BB 32
#define TT 512
#define DD 1024
#define HH 1024

// Scratch (device globals: allocation-free rule)
__device__ float g_xp[(size_t)TT * BB * 4 * HH];      // 256 MB  [m][gate*1024+j]
__device__ float g_states[(size_t)TT * BB * HH];      // 64 MB   [m][j]
__device__ float g_hT[(size_t)HH * BB];               // 128 KB  [j][b] (prev h, transposed)
__device__ unsigned g_bar_count = 0;
__device__ unsigned g_bar_gen = 0;

// ===========================================================================
// Kernel 1: input projection GEMM. M=16384 (m=t*32+b), N=4096, K=1024.
// 128x128 tile, BK=8, 256 threads, 8x8 per thread (split 64+64), double buffer
// ===========================================================================
__global__ void __launch_bounds__(256) k_input_gemm(
    const float* __restrict__ x,
    const float* __restrict__ Wi, const float* __restrict__ Wf,
    const float* __restrict__ Wg, const float* __restrict__ Wc,
    const float* __restrict__ bi, const float* __restrict__ bf,
    const float* __restrict__ bg, const float* __restrict__ bc)
{
    __shared__ float As[2][8][132];
    __shared__ float Bs[2][8][128];

    const int tid = threadIdx.x;
    const int tx = tid & 15;
    const int ty = tid >> 4;
    const int nblk = blockIdx.x * 128;
    const int mblk = blockIdx.y * 128;

    const int gate = nblk >> 10;
    const float* W    = (gate == 0) ? Wi : (gate == 1) ? Wf : (gate == 2) ? Wg : Wc;
    const float* bias = (gate == 0) ? bi : (gate == 1) ? bf : (gate == 2) ? bg : bc;
    const int jb = nblk & 1023;

    // A loader: thread -> (row_a = tid>>1 in [0,128), ka = (tid&1)*4)
    const int row_a = tid >> 1;
    const int ka = (tid & 1) * 4;
    const int m_a = mblk + row_a;                 // m = t*32 + b
    const float* arow = x + ((size_t)((m_a & 31) * TT + (m_a >> 5))) * DD;

    // B loader: thread -> (kb = tid>>5 in [0,8), nb = (tid&31)*4)
    const int kb = tid >> 5;
    const int nb = (tid & 31) * 4;

    // preload tile 0
    {
        float4 av = *(const float4*)&arow[ka];
        float4 bv = *(const float4*)&W[(size_t)kb * HH + jb + nb];
        As[0][ka + 0][row_a] = av.x;
        As[0][ka + 1][row_a] = av.y;
        As[0][ka + 2][row_a] = av.z;
        As[0][ka + 3][row_a] = av.w;
        *(float4*)&Bs[0][kb][nb] = bv;
    }
    __syncthreads();

    float acc[8][8];
#pragma unroll
    for (int r = 0; r < 8; ++r)
#pragma unroll
        for (int c = 0; c < 8; ++c) acc[r][c] = 0.0f;

#pragma unroll 1
    for (int k0 = 0; k0 < DD; k0 += 8) {
        const int cur = (k0 >> 3) & 1;
        float4 a_n, b_n;
        const bool more = (k0 + 8) < DD;
        if (more) {
            a_n = *(const float4*)&arow[k0 + 8 + ka];
            b_n = *(const float4*)&W[(size_t)(k0 + 8 + kb) * HH + jb + nb];
        }
#pragma unroll
        for (int kk = 0; kk < 8; ++kk) {
            float4 a0 = *(const float4*)&As[cur][kk][ty * 4];
            float4 a1 = *(const float4*)&As[cur][kk][64 + ty * 4];
            float4 b0 = *(const float4*)&Bs[cur][kk][tx * 4];
            float4 b1 = *(const float4*)&Bs[cur][kk][64 + tx * 4];
            float ar[8] = {a0.x, a0.y, a0.z, a0.w, a1.x, a1.y, a1.z, a1.w};
            float br[8] = {b0.x, b0.y, b0.z, b0.w, b1.x, b1.y, b1.z, b1.w};
#pragma unroll
            for (int r = 0; r < 8; ++r)
#pragma unroll
                for (int c = 0; c < 8; ++c)
                    acc[r][c] = fmaf(ar[r], br[c], acc[r][c]);
        }
        if (more) {
            const int nxt = cur ^ 1;
            As[nxt][ka + 0][row_a] = a_n.x;
            As[nxt][ka + 1][row_a] = a_n.y;
            As[nxt][ka + 2][row_a] = a_n.z;
            As[nxt][ka + 3][row_a] = a_n.w;
            *(float4*)&Bs[nxt][kb][nb] = b_n;
            __syncthreads();
        }
    }

    // epilogue: + bias, store to g_xp
#pragma unroll
    for (int ch = 0; ch < 2; ++ch) {
        const int cbase = ch * 64 + tx * 4;
        float4 bsv = *(const float4*)&bias[jb + cbase];
#pragma unroll
        for (int rh = 0; rh < 2; ++rh)
#pragma unroll
            for (int rr = 0; rr < 4; ++rr) {
                const int m = mblk + rh * 64 + ty * 4 + rr;
                float4 o;
                o.x = acc[rh * 4 + rr][ch * 4 + 0] + bsv.x;
                o.y = acc[rh * 4 + rr][ch * 4 + 1] + bsv.y;
                o.z = acc[rh * 4 + rr][ch * 4 + 2] + bsv.z;
                o.w = acc[rh * 4 + rr][ch * 4 + 3] + bsv.w;
                *(float4*)&g_xp[(size_t)m * 4096 + nblk + cbase] = o;
            }
    }
}

// ===========================================================================
// Kernel 2: persistent recurrent kernel.
// 128 blocks x 256 threads, 1 block/SM (192KB smem). Block: all 32 b x 8 j.
// Thread (bg=tid&7, jg=(tid>>3)&3, ks=tid>>5): 4 b x 2 j x 4 gates accums,
// k chunk of 128 (split across 2 phases of staged h halves).
// U resident in smem (128KB). h staged per step in [k][b] layout (64KB half).
// ===========================================================================
#define NBLK2 128
#define SH_U_FLOATS 32768           /* [1024][4][8] */
#define SH_H_FLOATS 16384           /* [512][32], aliased as red[8][32][34] */
#define SMEM2_BYTES ((SH_U_FLOATS + SH_H_FLOATS) * 4)

__device__ __forceinline__ void grid_sync()
{
    __syncthreads();
    if (threadIdx.x == 0) {
        __threadfence();
        unsigned gen = *(volatile unsigned*)&g_bar_gen;
        unsigned t = atomicAdd(&g_bar_count, 1);
        if (t == NBLK2 - 1) {
            g_bar_count = 0;
            __threadfence();
            atomicExch(&g_bar_gen, gen + 1);
        } else {
            while (*(volatile unsigned*)&g_bar_gen == gen) { }
            __threadfence();
        }
    }
    __syncthreads();
}

__global__ void __launch_bounds__(256, 1) k_recurrent(
    const float* __restrict__ Ui, const float* __restrict__ Uf,
    const float* __restrict__ Ug, const float* __restrict__ Uc)
{
    extern __shared__ float smem[];
    float* sh_u = smem;                 // [k:1024][g:4][jl:8]
    float* sh_h = smem + SH_U_FLOATS;   // [k_half:512][b:32]

    const int tid = threadIdx.x;
    const int bg = tid & 7;             // b0 = bg*4
    const int jg = (tid >> 3) & 3;      // local j pair: jg*2, jg*2+1
    const int ks = tid >> 5;            // k-split 0..7
    const int jb8 = blockIdx.x * 8;

    // stage U once: sh_u[(k*4+g)*8 + jl] = U_g[k][jb8+jl]
    for (int i = tid; i < 8192; i += 256) {
        const int k = i >> 3;
        const int g = (i >> 1) & 3;
        const int j4 = (i & 1) * 4;
        const float* Up = (g == 0) ? Ui : (g == 1) ? Uf : (g == 2) ? Ug : Uc;
        float4 v = *(const float4*)&Up[(size_t)k * HH + jb8 + j4];
        *(float4*)&sh_u[(k * 4 + g) * 8 + j4] = v;
    }

    // reduction identity: thread -> (rb, rj), owns c for (b=rb, j=jb8+rj)
    const int rb = tid >> 3;
    const int rj = tid & 7;
    float c = 0.0f;

    __syncthreads();

    for (int t = 0; t < TT; ++t) {
        float2 acc[4][4];               // [gate][bi]
#pragma unroll
        for (int g = 0; g < 4; ++g)
#pragma unroll
            for (int bi = 0; bi < 4; ++bi) acc[g][bi] = make_float2(0.f, 0.f);

#pragma unroll 1
        for (int p = 0; p < 2; ++p) {
            // stage h half: sh_h[kl*32+b] = h_prev[b][p*512+kl]
            if (t == 0) {
                for (int i = tid * 4; i < SH_H_FLOATS; i += 1024)
                    *(float4*)&sh_h[i] = make_float4(0.f, 0.f, 0.f, 0.f);
            } else {
                const float* src = g_hT + (size_t)p * 512 * 32;
                for (int i = tid * 4; i < SH_H_FLOATS; i += 1024)
                    *(float4*)&sh_h[i] = *(const float4*)&src[i];
            }
            __syncthreads();

            const float* hp = sh_h + (ks * 64) * 32 + bg * 4;
            const float* up = sh_u + (p * 512 + ks * 64) * 32 + jg * 2;
#pragma unroll 8
            for (int kk = 0; kk < 64; ++kk) {
                float4 hv = *(const float4*)&hp[kk * 32];
                const float* u = &up[kk * 32];
                float2 uu0 = *(const float2*)&u[0];
                float2 uu1 = *(const float2*)&u[8];
                float2 uu2 = *(const float2*)&u[16];
                float2 uu3 = *(const float2*)&u[24];
                float h4[4] = {hv.x, hv.y, hv.z, hv.w};
                float2 uu[4] = {uu0, uu1, uu2, uu3};
#pragma unroll
                for (int g = 0; g < 4; ++g)
#pragma unroll
                    for (int bi = 0; bi < 4; ++bi) {
                        acc[g][bi].x = fmaf(h4[bi], uu[g].x, acc[g][bi].x);
                        acc[g][bi].y = fmaf(h4[bi], uu[g].y, acc[g][bi].y);
                    }
            }
            __syncthreads();
        }

        // write partials: red[ks][b][col], stride 34 per b, col = g*8 + jl
        float* sh_red = sh_h;
#pragma unroll
        for (int g = 0; g < 4; ++g)
#pragma unroll
            for (int bi = 0; bi < 4; ++bi)
                *(float2*)&sh_red[ks * 1088 + (bg * 4 + bi) * 34 + g * 8 + jg * 2] =
                    acc[g][bi];
        __syncthreads();

        // reduce 8 partials per (b, gate, j) + gate math
        float z[4];
#pragma unroll
        for (int g = 0; g < 4; ++g) {
            float s = 0.0f;
#pragma unroll
            for (int q = 0; q < 8; ++q)
                s += sh_red[q * 1088 + rb * 34 + g * 8 + rj];
            z[g] = s;
        }
        const float* xp = g_xp + ((size_t)t * 32 + rb) * 4096 + jb8 + rj;
        float zi = z[0] + xp[0];
        float zf = z[1] + xp[1024];
        float zg = z[2] + xp[2048];
        float zc = z[3] + xp[3072];

        float ig = 1.0f / (1.0f + __expf(-zi));
        float fg = 1.0f / (1.0f + __expf(-zf));
        float gg = 1.0f / (1.0f + __expf(-zg));
        float ct = tanhf(zc);
        c = fg * c + ig * ct;
        float h = gg * tanhf(c);

        g_states[((size_t)t * 32 + rb) * HH + jb8 + rj] = h;
        g_hT[(size_t)(jb8 + rj) * 32 + rb] = h;

        grid_sync();
    }
}

// ===========================================================================
// Kernel 3: output projection + ReLU. M=16384, N=1024, K=1024.
// Same 128x128x8 double-buffered structure as k1.
// ===========================================================================
__global__ void __launch_bounds__(256) k_output_gemm(
    const float* __restrict__ Wo, const float* __restrict__ bo,
    float* __restrict__ out)
{
    __shared__ float As[2][8][132];
    __shared__ float Bs[2][8][128];

    const int tid = threadIdx.x;
    const int tx = tid & 15;
    const int ty = tid >> 4;
    const int nblk = blockIdx.x * 128;
    const int mblk = blockIdx.y * 128;

    const int row_a = tid >> 1;
    const int ka = (tid & 1) * 4;
    const float* arow = g_states + (size_t)(mblk + row_a) * HH;

    const int kb = tid >> 5;
    const int nb = (tid & 31) * 4;

    {
        float4 av = *(const float4*)&arow[ka];
        float4 bv = *(const float4*)&Wo[(size_t)kb * HH + nblk + nb];
        As[0][ka + 0][row_a] = av.x;
        As[0][ka + 1][row_a] = av.y;
        As[0][ka + 2][row_a] = av.z;
        As[0][ka + 3][row_a] = av.w;
        *(float4*)&Bs[0][kb][nb] = bv;
    }
    __syncthreads();

    float acc[8][8];
#pragma unroll
    for (int r = 0; r < 8; ++r)
#pragma unroll
        for (int c = 0; c < 8; ++c) acc[r][c] = 0.0f;

#pragma unroll 1
    for (int k0 = 0; k0 < HH; k0 += 8) {
        const int cur = (k0 >> 3) & 1;
        float4 a_n, b_n;
        const bool more = (k0 + 8) < HH;
        if (more) {
            a_n = *(const float4*)&arow[k0 + 8 + ka];
            b_n = *(const float4*)&Wo[(size_t)(k0 + 8 + kb) * HH + nblk + nb];
        }
#pragma unroll
        for (int kk = 0; kk < 8; ++kk) {
            float4 a0 = *(const float4*)&As[cur][kk][ty * 4];
            float4 a1 = *(const float4*)&As[cur][kk][64 + ty * 4];
            float4 b0 = *(const float4*)&Bs[cur][kk][tx * 4];
            float4 b1 = *(const float4*)&Bs[cur][kk][64 + tx * 4];
            float ar[8] = {a0.x, a0.y, a0.z, a0.w, a1.x, a1.y, a1.z, a1.w};
            float br[8] = {b0.x, b0.y, b0.z, b0.w, b1.x, b1.y, b1.z, b1.w};
#pragma unroll
            for (int r = 0; r < 8; ++r)
#pragma unroll
                for (int c = 0; c < 8; ++c)
                    acc[r][c] = fmaf(ar[r], br[c], acc[r][c]);
        }
        if (more) {
            const int nxt = cur ^ 1;
            As[nxt][ka + 0][row_a] = a_n.x;
            As[nxt][ka + 1][row_a] = a_n.y;
            As[nxt][ka + 2][row_a] = a_n.z;
            As[nxt][ka + 3][row_a] = a_n.w;
            *(float4*)&Bs[nxt][kb][nb] = b_n;
            __syncthreads();
        }
    }

#pragma unroll
    for (int ch = 0; ch < 2; ++ch) {
        const int cbase = ch * 64 + tx * 4;
        float4 bsv = *(const float4*)&bo[nblk + cbase];
#pragma unroll
        for (int rh = 0; rh < 2; ++rh)
#pragma unroll
            for (int rr = 0; rr < 4; ++rr) {
                const int m = mblk + rh * 64 + ty * 4 + rr;   // m = t*32 + b
                const int b = m & 31;
                const int tt = m >> 5;
                float4 o;
                o.x = fmaxf(acc[rh * 4 + rr][ch * 4 + 0] + bsv.x, 0.0f);
                o.y = fmaxf(acc[rh * 4 + rr][ch * 4 + 1] + bsv.y, 0.0f);
                o.z = fmaxf(acc[rh * 4 + rr][ch * 4 + 2] + bsv.z, 0.0f);
                o.w = fmaxf(acc[rh * 4 + rr][ch * 4 + 3] + bsv.w, 0.0f);
                *(float4*)&out[((size_t)b * TT + tt) * HH + nblk + cbase] = o;
            }
    }
}

// ---------------------------------------------------------------------------
// Launch
// ---------------------------------------------------------------------------
extern "C" void kernel_launch(void* const* d_in, const int* in_sizes, int n_in,
                              void* d_out, int out_size)
{
    const float* x  = (const float*)d_in[0];
    const float* Wi = (const float*)d_in[1];
    const float* Ui = (const float*)d_in[2];
    const float* Wf = (const float*)d_in[3];
    const float* Uf = (const float*)d_in[4];
    const float* Wg = (const float*)d_in[5];
    const float* Ug = (const float*)d_in[6];
    const float* Wc = (const float*)d_in[7];
    const float* Uc = (const float*)d_in[8];
    const float* Wo = (const float*)d_in[9];
    const float* bi = (const float*)d_in[10];
    const float* bf = (const float*)d_in[11];
    const float* bg = (const float*)d_in[12];
    const float* bc = (const float*)d_in[13];
    const float* bo = (const float*)d_in[14];
    float* out = (float*)d_out;

    static bool attr_set = false;
    if (!attr_set) {
        cudaFuncSetAttribute(k_recurrent,
                             cudaFuncAttributeMaxDynamicSharedMemorySize,
                             SMEM2_BYTES);
        attr_set = true;
    }

    // 1) input projection: grid (4096/128, 16384/128)
    k_input_gemm<<<dim3(32, 128), 256>>>(x, Wi, Wf, Wg, Wc, bi, bf, bg, bc);

    // 2) recurrence: persistent kernel, 128 blocks, 192KB smem
    k_recurrent<<<NBLK2, 256, SMEM2_BYTES>>>(Ui, Uf, Ug, Uc);

    // 3) output projection: grid (1024/128, 16384/128)
    k_output_gemm<<<dim3(8, 128), 256>>>(Wo, bo, out);
}

// round 4
// speedup vs baseline: 2.2072x; 1.0538x over previous
#include <cuda_runtime.h>
#include <math.h>

// ---------------------------------------------------------------------------
// LSTM layer: B=32, T=512, D=1024, H=1024 — packed fp32x2 (FFMA2) version
// ---------------------------------------------------------------------------

#define BB 32
#define TT 512
#define DD 1024
#define HH 1024

typedef unsigned long long u64;

__device__ __forceinline__ u64 pack2(float x, float y) {
    u64 r; asm("mov.b64 %0, {%1, %2};" : "=l"(r) : "f"(x), "f"(y)); return r;
}
__device__ __forceinline__ void ffma2(u64 &d, u64 a, u64 b) {
    asm("fma.rn.f32x2 %0, %1, %2, %0;" : "+l"(d) : "l"(a), "l"(b));
}
__device__ __forceinline__ float2 unpack2(u64 v) {
    float2 f; asm("mov.b64 {%0, %1}, %2;" : "=f"(f.x), "=f"(f.y) : "l"(v)); return f;
}

// Scratch (device globals: allocation-free rule)
__device__ float g_xp[(size_t)TT * BB * 4 * HH];      // 256 MB  [m][gate*1024+j]
__device__ float g_states[(size_t)TT * BB * HH];      // 64 MB   [m][j]
__device__ float g_hT[(size_t)HH * BB];               // 128 KB  [j][b]
__device__ unsigned g_bar_count = 0;
__device__ unsigned g_bar_gen = 0;

// ===========================================================================
// Kernel 1: input projection GEMM. M=16384 (m=t*32+b), N=4096, K=1024.
// 128x128 tile, BK=8, 256 threads, 8x8 per thread via FFMA2, double buffer.
// As stored DUPLICATED: As[k][2m] = As[k][2m+1] = a[m]  (broadcast pairs free)
// ===========================================================================
__global__ void __launch_bounds__(256) k_input_gemm(
    const float* __restrict__ x,
    const float* __restrict__ Wi, const float* __restrict__ Wf,
    const float* __restrict__ Wg, const float* __restrict__ Wc,
    const float* __restrict__ bi, const float* __restrict__ bf,
    const float* __restrict__ bg, const float* __restrict__ bc)
{
    __shared__ float As[2][8][264];   // duplicated, padded
    __shared__ float Bs[2][8][128];

    const int tid = threadIdx.x;
    const int tx = tid & 15;
    const int ty = tid >> 4;
    const int nblk = blockIdx.x * 128;
    const int mblk = blockIdx.y * 128;

    const int gate = nblk >> 10;
    const float* W    = (gate == 0) ? Wi : (gate == 1) ? Wf : (gate == 2) ? Wg : Wc;
    const float* bias = (gate == 0) ? bi : (gate == 1) ? bf : (gate == 2) ? bg : bc;
    const int jb = nblk & 1023;

    // A loader: thread -> (row_a = tid>>1 in [0,128), ka = (tid&1)*4)
    const int row_a = tid >> 1;
    const int ka = (tid & 1) * 4;
    const int m_a = mblk + row_a;                 // m = t*32 + b
    const float* arow = x + ((size_t)((m_a & 31) * TT + (m_a >> 5))) * DD;

    // B loader
    const int kb = tid >> 5;
    const int nb = (tid & 31) * 4;

    // preload tile 0
    {
        float4 av = *(const float4*)&arow[ka];
        float4 bv = *(const float4*)&W[(size_t)kb * HH + jb + nb];
        *(float2*)&As[0][ka + 0][2 * row_a] = make_float2(av.x, av.x);
        *(float2*)&As[0][ka + 1][2 * row_a] = make_float2(av.y, av.y);
        *(float2*)&As[0][ka + 2][2 * row_a] = make_float2(av.z, av.z);
        *(float2*)&As[0][ka + 3][2 * row_a] = make_float2(av.w, av.w);
        *(float4*)&Bs[0][kb][nb] = bv;
    }
    __syncthreads();

    u64 acc2[8][4];
#pragma unroll
    for (int r = 0; r < 8; ++r)
#pragma unroll
        for (int c = 0; c < 4; ++c) acc2[r][c] = 0ull;

#pragma unroll 1
    for (int k0 = 0; k0 < DD; k0 += 8) {
        const int cur = (k0 >> 3) & 1;
        float4 a_n, b_n;
        const bool more = (k0 + 8) < DD;
        if (more) {
            a_n = *(const float4*)&arow[k0 + 8 + ka];
            b_n = *(const float4*)&W[(size_t)(k0 + 8 + kb) * HH + jb + nb];
        }
#pragma unroll
        for (int kk = 0; kk < 8; ++kk) {
            ulonglong2 al0 = *(const ulonglong2*)&As[cur][kk][8 * ty];
            ulonglong2 al1 = *(const ulonglong2*)&As[cur][kk][8 * ty + 4];
            ulonglong2 au0 = *(const ulonglong2*)&As[cur][kk][128 + 8 * ty];
            ulonglong2 au1 = *(const ulonglong2*)&As[cur][kk][128 + 8 * ty + 4];
            ulonglong2 bl = *(const ulonglong2*)&Bs[cur][kk][tx * 4];
            ulonglong2 bu = *(const ulonglong2*)&Bs[cur][kk][64 + tx * 4];
            u64 ab[8] = {al0.x, al0.y, al1.x, al1.y, au0.x, au0.y, au1.x, au1.y};
            u64 bb[4] = {bl.x, bl.y, bu.x, bu.y};
#pragma unroll
            for (int r = 0; r < 8; ++r)
#pragma unroll
                for (int c = 0; c < 4; ++c)
                    ffma2(acc2[r][c], ab[r], bb[c]);
        }
        if (more) {
            const int nxt = cur ^ 1;
            *(float2*)&As[nxt][ka + 0][2 * row_a] = make_float2(a_n.x, a_n.x);
            *(float2*)&As[nxt][ka + 1][2 * row_a] = make_float2(a_n.y, a_n.y);
            *(float2*)&As[nxt][ka + 2][2 * row_a] = make_float2(a_n.z, a_n.z);
            *(float2*)&As[nxt][ka + 3][2 * row_a] = make_float2(a_n.w, a_n.w);
            *(float4*)&Bs[nxt][kb][nb] = b_n;
            __syncthreads();
        }
    }

    // epilogue: + bias, store to g_xp
#pragma unroll
    for (int ch = 0; ch < 2; ++ch) {
        const int cbase = ch * 64 + tx * 4;
        float4 bsv = *(const float4*)&bias[jb + cbase];
#pragma unroll
        for (int rh = 0; rh < 2; ++rh)
#pragma unroll
            for (int rr = 0; rr < 4; ++rr) {
                const int m = mblk + rh * 64 + ty * 4 + rr;
                float2 p0 = unpack2(acc2[rh * 4 + rr][ch * 2 + 0]);
                float2 p1 = unpack2(acc2[rh * 4 + rr][ch * 2 + 1]);
                float4 o;
                o.x = p0.x + bsv.x;
                o.y = p0.y + bsv.y;
                o.z = p1.x + bsv.z;
                o.w = p1.y + bsv.w;
                *(float4*)&g_xp[(size_t)m * 4096 + nblk + cbase] = o;
            }
    }
}

// ===========================================================================
// Kernel 2: persistent recurrent kernel (FFMA2 inner loop).
// 128 blocks x 256 threads, 1 block/SM (192KB smem). Block: all 32 b x 8 j.
// ===========================================================================
#define NBLK2 128
#define SH_U_FLOATS 32768           /* [1024][4][8] */
#define SH_H_FLOATS 16384           /* [512][32], aliased as red[8][32][34] */
#define SMEM2_BYTES ((SH_U_FLOATS + SH_H_FLOATS) * 4)

__device__ __forceinline__ void grid_sync()
{
    __syncthreads();
    if (threadIdx.x == 0) {
        __threadfence();
        unsigned gen = *(volatile unsigned*)&g_bar_gen;
        unsigned t = atomicAdd(&g_bar_count, 1);
        if (t == NBLK2 - 1) {
            g_bar_count = 0;
            __threadfence();
            atomicExch(&g_bar_gen, gen + 1);
        } else {
            while (*(volatile unsigned*)&g_bar_gen == gen) { }
            __threadfence();
        }
    }
    __syncthreads();
}

__global__ void __launch_bounds__(256, 1) k_recurrent(
    const float* __restrict__ Ui, const float* __restrict__ Uf,
    const float* __restrict__ Ug, const float* __restrict__ Uc)
{
    extern __shared__ float smem[];
    float* sh_u = smem;                 // [k:1024][g:4][jl:8]
    float* sh_h = smem + SH_U_FLOATS;   // [k_half:512][b:32]

    const int tid = threadIdx.x;
    const int bg = tid & 7;             // b0 = bg*4
    const int jg = (tid >> 3) & 3;      // local j pair: jg*2, jg*2+1
    const int ks = tid >> 5;            // k-split 0..7
    const int jb8 = blockIdx.x * 8;

    // stage U once: sh_u[(k*4+g)*8 + jl] = U_g[k][jb8+jl]
    for (int i = tid; i < 8192; i += 256) {
        const int k = i >> 3;
        const int g = (i >> 1) & 3;
        const int j4 = (i & 1) * 4;
        const float* Up = (g == 0) ? Ui : (g == 1) ? Uf : (g == 2) ? Ug : Uc;
        float4 v = *(const float4*)&Up[(size_t)k * HH + jb8 + j4];
        *(float4*)&sh_u[(k * 4 + g) * 8 + j4] = v;
    }

    // reduction identity: thread -> (rb, rj), owns c for (b=rb, j=jb8+rj)
    const int rb = tid >> 3;
    const int rj = tid & 7;
    float c = 0.0f;

    __syncthreads();

    for (int t = 0; t < TT; ++t) {
        u64 acc2[4][4];                 // [gate][bi] packed j-pair
#pragma unroll
        for (int g = 0; g < 4; ++g)
#pragma unroll
            for (int bi = 0; bi < 4; ++bi) acc2[g][bi] = 0ull;

#pragma unroll 1
        for (int p = 0; p < 2; ++p) {
            // stage h half: sh_h[kl*32+b] = h_prev[b][p*512+kl]
            if (t == 0) {
                for (int i = tid * 4; i < SH_H_FLOATS; i += 1024)
                    *(float4*)&sh_h[i] = make_float4(0.f, 0.f, 0.f, 0.f);
            } else {
                const float* src = g_hT + (size_t)p * 512 * 32;
                for (int i = tid * 4; i < SH_H_FLOATS; i += 1024)
                    *(float4*)&sh_h[i] = *(const float4*)&src[i];
            }
            __syncthreads();

            const float* hp = sh_h + (ks * 64) * 32 + bg * 4;
            const float* up = sh_u + (p * 512 + ks * 64) * 32 + jg * 2;
#pragma unroll 8
            for (int kk = 0; kk < 64; ++kk) {
                float4 hv = *(const float4*)&hp[kk * 32];
                const float* u = &up[kk * 32];
                u64 u0 = *(const u64*)&u[0];
                u64 u1 = *(const u64*)&u[8];
                u64 u2 = *(const u64*)&u[16];
                u64 u3 = *(const u64*)&u[24];
                u64 hb[4];
                hb[0] = pack2(hv.x, hv.x);
                hb[1] = pack2(hv.y, hv.y);
                hb[2] = pack2(hv.z, hv.z);
                hb[3] = pack2(hv.w, hv.w);
                u64 uu[4] = {u0, u1, u2, u3};
#pragma unroll
                for (int g = 0; g < 4; ++g)
#pragma unroll
                    for (int bi = 0; bi < 4; ++bi)
                        ffma2(acc2[g][bi], hb[bi], uu[g]);
            }
            __syncthreads();
        }

        // write partials: red[ks][b][col], stride 34 per b, col = g*8 + jl
        float* sh_red = sh_h;
#pragma unroll
        for (int g = 0; g < 4; ++g)
#pragma unroll
            for (int bi = 0; bi < 4; ++bi)
                *(u64*)&sh_red[ks * 1088 + (bg * 4 + bi) * 34 + g * 8 + jg * 2] =
                    acc2[g][bi];
        __syncthreads();

        // reduce 8 partials per (b, gate, j) + gate math
        float z[4];
#pragma unroll
        for (int g = 0; g < 4; ++g) {
            float s = 0.0f;
#pragma unroll
            for (int q = 0; q < 8; ++q)
                s += sh_red[q * 1088 + rb * 34 + g * 8 + rj];
            z[g] = s;
        }
        const float* xp = g_xp + ((size_t)t * 32 + rb) * 4096 + jb8 + rj;
        float zi = z[0] + xp[0];
        float zf = z[1] + xp[1024];
        float zg = z[2] + xp[2048];
        float zc = z[3] + xp[3072];

        float ig = 1.0f / (1.0f + __expf(-zi));
        float fg = 1.0f / (1.0f + __expf(-zf));
        float gg = 1.0f / (1.0f + __expf(-zg));
        float ct = tanhf(zc);
        c = fg * c + ig * ct;
        float h = gg * tanhf(c);

        g_states[((size_t)t * 32 + rb) * HH + jb8 + rj] = h;
        g_hT[(size_t)(jb8 + rj) * 32 + rb] = h;

        grid_sync();
    }
}

// ===========================================================================
// Kernel 3: output projection + ReLU. M=16384, N=1024, K=1024. FFMA2.
// ===========================================================================
__global__ void __launch_bounds__(256) k_output_gemm(
    const float* __restrict__ Wo, const float* __restrict__ bo,
    float* __restrict__ out)
{
    __shared__ float As[2][8][264];
    __shared__ float Bs[2][8][128];

    const int tid = threadIdx.x;
    const int tx = tid & 15;
    const int ty = tid >> 4;
    const int nblk = blockIdx.x * 128;
    const int mblk = blockIdx.y * 128;

    const int row_a = tid >> 1;
    const int ka = (tid & 1) * 4;
    const float* arow = g_states + (size_t)(mblk + row_a) * HH;

    const int kb = tid >> 5;
    const int nb = (tid & 31) * 4;

    {
        float4 av = *(const float4*)&arow[ka];
        float4 bv = *(const float4*)&Wo[(size_t)kb * HH + nblk + nb];
        *(float2*)&As[0][ka + 0][2 * row_a] = make_float2(av.x, av.x);
        *(float2*)&As[0][ka + 1][2 * row_a] = make_float2(av.y, av.y);
        *(float2*)&As[0][ka + 2][2 * row_a] = make_float2(av.z, av.z);
        *(float2*)&As[0][ka + 3][2 * row_a] = make_float2(av.w, av.w);
        *(float4*)&Bs[0][kb][nb] = bv;
    }
    __syncthreads();

    u64 acc2[8][4];
#pragma unroll
    for (int r = 0; r < 8; ++r)
#pragma unroll
        for (int c = 0; c < 4; ++c) acc2[r][c] = 0ull;

#pragma unroll 1
    for (int k0 = 0; k0 < HH; k0 += 8) {
        const int cur = (k0 >> 3) & 1;
        float4 a_n, b_n;
        const bool more = (k0 + 8) < HH;
        if (more) {
            a_n = *(const float4*)&arow[k0 + 8 + ka];
            b_n = *(const float4*)&Wo[(size_t)(k0 + 8 + kb) * HH + nblk + nb];
        }
#pragma unroll
        for (int kk = 0; kk < 8; ++kk) {
            ulonglong2 al0 = *(const ulonglong2*)&As[cur][kk][8 * ty];
            ulonglong2 al1 = *(const ulonglong2*)&As[cur][kk][8 * ty + 4];
            ulonglong2 au0 = *(const ulonglong2*)&As[cur][kk][128 + 8 * ty];
            ulonglong2 au1 = *(const ulonglong2*)&As[cur][kk][128 + 8 * ty + 4];
            ulonglong2 bl = *(const ulonglong2*)&Bs[cur][kk][tx * 4];
            ulonglong2 bu = *(const ulonglong2*)&Bs[cur][kk][64 + tx * 4];
            u64 ab[8] = {al0.x, al0.y, al1.x, al1.y, au0.x, au0.y, au1.x, au1.y};
            u64 bb[4] = {bl.x, bl.y, bu.x, bu.y};
#pragma unroll
            for (int r = 0; r < 8; ++r)
#pragma unroll
                for (int c = 0; c < 4; ++c)
                    ffma2(acc2[r][c], ab[r], bb[c]);
        }
        if (more) {
            const int nxt = cur ^ 1;
            *(float2*)&As[nxt][ka + 0][2 * row_a] = make_float2(a_n.x, a_n.x);
            *(float2*)&As[nxt][ka + 1][2 * row_a] = make_float2(a_n.y, a_n.y);
            *(float2*)&As[nxt][ka + 2][2 * row_a] = make_float2(a_n.z, a_n.z);
            *(float2*)&As[nxt][ka + 3][2 * row_a] = make_float2(a_n.w, a_n.w);
            *(float4*)&Bs[nxt][kb][nb] = b_n;
            __syncthreads();
        }
    }

#pragma unroll
    for (int ch = 0; ch < 2; ++ch) {
        const int cbase = ch * 64 + tx * 4;
        float4 bsv = *(const float4*)&bo[nblk + cbase];
#pragma unroll
        for (int rh = 0; rh < 2; ++rh)
#pragma unroll
            for (int rr = 0; rr < 4; ++rr) {
                const int m = mblk + rh * 64 + ty * 4 + rr;   // m = t*32 + b
                const int b = m & 31;
                const int tt = m >> 5;
                float2 p0 = unpack2(acc2[rh * 4 + rr][ch * 2 + 0]);
                float2 p1 = unpack2(acc2[rh * 4 + rr][ch * 2 + 1]);
                float4 o;
                o.x = fmaxf(p0.x + bsv.x, 0.0f);
                o.y = fmaxf(p0.y + bsv.y, 0.0f);
                o.z = fmaxf(p1.x + bsv.z, 0.0f);
                o.w = fmaxf(p1.y + bsv.w, 0.0f);
                *(float4*)&out[((size_t)b * TT + tt) * HH + nblk + cbase] = o;
            }
    }
}

// ---------------------------------------------------------------------------
// Launch
// ---------------------------------------------------------------------------
extern "C" void kernel_launch(void* const* d_in, const int* in_sizes, int n_in,
                              void* d_out, int out_size)
{
    const float* x  = (const float*)d_in[0];
    const float* Wi = (const float*)d_in[1];
    const float* Ui = (const float*)d_in[2];
    const float* Wf = (const float*)d_in[3];
    const float* Uf = (const float*)d_in[4];
    const float* Wg = (const float*)d_in[5];
    const float* Ug = (const float*)d_in[6];
    const float* Wc = (const float*)d_in[7];
    const float* Uc = (const float*)d_in[8];
    const float* Wo = (const float*)d_in[9];
    const float* bi = (const float*)d_in[10];
    const float* bf = (const float*)d_in[11];
    const float* bg = (const float*)d_in[12];
    const float* bc = (const float*)d_in[13];
    const float* bo = (const float*)d_in[14];
    float* out = (float*)d_out;

    static bool attr_set = false;
    if (!attr_set) {
        cudaFuncSetAttribute(k_recurrent,
                             cudaFuncAttributeMaxDynamicSharedMemorySize,
                             SMEM2_BYTES);
        attr_set = true;
    }

    // 1) input projection: grid (4096/128, 16384/128)
    k_input_gemm<<<dim3(32, 128), 256>>>(x, Wi, Wf, Wg, Wc, bi, bf, bg, bc);

    // 2) recurrence: persistent kernel, 128 blocks, 192KB smem
    k_recurrent<<<NBLK2, 256, SMEM2_BYTES>>>(Ui, Uf, Ug, Uc);

    // 3) output projection: grid (1024/128, 16384/128)
    k_output_gemm<<<dim3(8, 128), 256>>>(Wo, bo, out);
}